// round 12
// baseline (speedup 1.0000x reference)
#include <cuda_runtime.h>
#include <cuda_bf16.h>
#include <stdint.h>
#include <math.h>

// QuadraticLorentzAttention via mma.sync bf16 (plain-sm_100-safe).
// s = <qs,ks> - t_q t_k <= -1 on-hyperboloid => no-max softmax, p=exp(s+64).
// R10/R11: explicit software-pipelined LDSM->MMA (ping-pong fragment regs) in
// QK and PV + warp phase rotation. Staging/sync/math identical to R6.
// (R11: resubmit after broker infra failure.)

namespace {
constexpr int N_SEQ = 2048;
constexpr int D     = 65;
constexpr int BQ    = 128;    // 8 warps x 16 query rows
constexpr int BK    = 64;
constexpr int THREADS = 256;
constexpr int BHMAX = 32;
constexpr float SHIFT = 64.0f;

constexpr int QS = 88;        // Q/K smem row stride (bf16): 176B
constexpr uint32_t OFF_QH = 0;
constexpr uint32_t OFF_QL = 22528;
constexpr uint32_t SMEM_TOTAL = 86016;
}

__device__ __forceinline__ uint32_t kh_off(int b) { return b ? 0u     : 45056u; }
__device__ __forceinline__ uint32_t kl_off(int b) { return b ? 11264u : 56320u; }
__device__ __forceinline__ uint32_t vh_off(int b) { return b ? 22528u : 67584u; }
__device__ __forceinline__ uint32_t vl_off(int b) { return b ? 31744u : 76800u; }

__device__ __align__(128) __nv_bfloat16 g_qh[(size_t)BHMAX * N_SEQ * 80];
__device__ __align__(128) __nv_bfloat16 g_ql[(size_t)BHMAX * N_SEQ * 80];
__device__ __align__(128) __nv_bfloat16 g_kh[(size_t)BHMAX * N_SEQ * 80];
__device__ __align__(128) __nv_bfloat16 g_kl[(size_t)BHMAX * N_SEQ * 80];
__device__ __align__(128) __nv_bfloat16 g_vh[(size_t)BHMAX * N_SEQ * 64];
__device__ __align__(128) __nv_bfloat16 g_vl[(size_t)BHMAX * N_SEQ * 64];

__device__ __forceinline__ uint32_t smem_u32(const void* p) {
    uint32_t a;
    asm("{ .reg .u64 t; cvta.to.shared.u64 t, %1; cvt.u32.u64 %0, t; }" : "=r"(a) : "l"(p));
    return a;
}
__device__ __forceinline__ void ldm_x4(uint32_t* r, uint32_t a) {
    asm volatile("ldmatrix.sync.aligned.m8n8.x4.shared.b16 {%0,%1,%2,%3}, [%4];"
                 : "=r"(r[0]), "=r"(r[1]), "=r"(r[2]), "=r"(r[3]) : "r"(a) : "memory");
}
__device__ __forceinline__ void ldm_x4t(uint32_t* r, uint32_t a) {
    asm volatile("ldmatrix.sync.aligned.m8n8.x4.trans.shared.b16 {%0,%1,%2,%3}, [%4];"
                 : "=r"(r[0]), "=r"(r[1]), "=r"(r[2]), "=r"(r[3]) : "r"(a) : "memory");
}
__device__ __forceinline__ void mma_bf16(float* c, const uint32_t* a, const uint32_t* b) {
    asm volatile("mma.sync.aligned.m16n8k16.row.col.f32.bf16.bf16.f32 "
                 "{%0,%1,%2,%3}, {%4,%5,%6,%7}, {%8,%9}, {%0,%1,%2,%3};"
                 : "+f"(c[0]), "+f"(c[1]), "+f"(c[2]), "+f"(c[3])
                 : "r"(a[0]), "r"(a[1]), "r"(a[2]), "r"(a[3]), "r"(b[0]), "r"(b[1]));
}
__device__ __forceinline__ uint32_t cvt_bf16x2(float lo, float hi) {
    uint32_t r;
    asm("cvt.rn.satfinite.bf16x2.f32 %0, %1, %2;" : "=r"(r) : "f"(hi), "f"(lo));
    return r;
}
__device__ __forceinline__ void cpa16(uint32_t dst, const void* src) {
    asm volatile("cp.async.cg.shared.global [%0], [%1], 16;" :: "r"(dst), "l"(src) : "memory");
}
#define CP_COMMIT() asm volatile("cp.async.commit_group;" ::: "memory")
#define CP_WAIT1()  asm volatile("cp.async.wait_group 1;" ::: "memory")

// ---------------- prep: fp32 -> bf16 hi/lo global layout ----------------
__global__ void __launch_bounds__(256)
prep_kernel(const float* __restrict__ Q, const float* __restrict__ K,
            const float* __restrict__ V, int BH)
{
    const int row = blockIdx.x * 8 + (threadIdx.x >> 5);
    const int ln  = threadIdx.x & 31;
    if (row >= BH * N_SEQ) return;
    const float* q = Q + (size_t)row * D;
    const float* k = K + (size_t)row * D;
    const float* v = V + (size_t)row * D;
    const size_t o80 = (size_t)row * 80, o64 = (size_t)row * 64;

    #pragma unroll
    for (int h = 0; h < 2; h++) {
        const int d = ln + 32 * h;
        const float qv = q[1 + d], kv = k[1 + d], vv = v[1 + d];
        __nv_bfloat16 x;
        x = __float2bfloat16(qv); g_qh[o80 + d] = x; g_ql[o80 + d] = __float2bfloat16(qv - __bfloat162float(x));
        x = __float2bfloat16(kv); g_kh[o80 + d] = x; g_kl[o80 + d] = __float2bfloat16(kv - __bfloat162float(x));
        x = __float2bfloat16(vv); g_vh[o64 + d] = x; g_vl[o64 + d] = __float2bfloat16(vv - __bfloat162float(x));
    }
    if (ln == 0) {
        const float tq = q[0];
        __nv_bfloat16 h = __float2bfloat16(tq);
        g_qh[o80 + 64] = h; g_ql[o80 + 64] = __float2bfloat16(tq - __bfloat162float(h));
        const float tk = -k[0];
        h = __float2bfloat16(tk);
        g_kh[o80 + 64] = h; g_kl[o80 + 64] = __float2bfloat16(tk - __bfloat162float(h));
    } else if (ln < 16) {
        const __nv_bfloat16 z = __float2bfloat16(0.f);
        g_qh[o80 + 64 + ln] = z; g_ql[o80 + 64 + ln] = z;
        g_kh[o80 + 64 + ln] = z; g_kl[o80 + 64 + ln] = z;
    }
}

// ---------------- main attention kernel ----------------
extern __shared__ char smem_raw[];

__device__ __forceinline__ void issue_kv(uint32_t sb, int buf, int kbase, int t) {
    const uint32_t khd = sb + kh_off(buf), kld = sb + kl_off(buf);
    const uint32_t vhd = sb + vh_off(buf), vld = sb + vl_off(buf);
    #pragma unroll
    for (int it = 0; it < 9; it++) {
        const int c = t + it * 256;
        if (c < 1280) {
            const int half = c >= 640;
            const int cc = c - half * 640;
            const int row = cc / 10, ch = cc - row * 10;
            const __nv_bfloat16* src = (half ? g_kl : g_kh) + ((size_t)(kbase + row)) * 80 + ch * 8;
            cpa16((half ? kld : khd) + row * 176 + ch * 16, src);
        } else {
            const int cc0 = c - 1280;
            const int half = cc0 >= 512;
            const int cc = cc0 - half * 512;
            const int row = cc >> 3, ch = cc & 7;
            const __nv_bfloat16* src = (half ? g_vl : g_vh) + ((size_t)(kbase + row)) * 64 + ch * 8;
            cpa16((half ? vld : vhd) + row * 144 + ch * 16, src);
        }
    }
}

__global__ void __launch_bounds__(THREADS, 2)
lorentz_attn_mma(const int* __restrict__ causal_p, float* __restrict__ Og)
{
    const uint32_t sb = smem_u32(smem_raw);
    const int t  = threadIdx.x;
    const int w  = t >> 5;
    const int ln = t & 31;
    const int g  = ln >> 2;
    const int tg = ln & 3;
    const int wrot = w & 3;                             // phase rotation
    const int bh = blockIdx.y;
    const int q0 = (gridDim.x - 1 - blockIdx.x) * BQ;   // heavy causal tiles first
    const int cz = *causal_p;
    const size_t obase = (size_t)bh * N_SEQ * D;

    const int arow = (ln & 7) + ((ln >> 3) & 1) * 8;    // A-frag addressing
    const int adim = (ln >> 4) * 8;
    const int ntiles = cz ? (q0 >> 6) + 2 : (N_SEQ / BK);
    const int qbase = bh * N_SEQ + q0;
    const int kvbase = bh * N_SEQ;

    // ---- stage Q (group Gq), then K/V tile 0 (G0) ----
    #pragma unroll
    for (int it = 0; it < 10; it++) {
        const int c = t + it * 256;
        const int half = c >= 1280;
        const int cc = c - half * 1280;
        const int row = cc / 10, ch = cc - row * 10;
        const __nv_bfloat16* src = (half ? g_ql : g_qh) + ((size_t)(qbase + row)) * 80 + ch * 8;
        cpa16(sb + (half ? OFF_QL : OFF_QH) + row * 176 + ch * 16, src);
    }
    CP_COMMIT();
    issue_kv(sb, 0, kvbase, t);
    CP_COMMIT();
    CP_WAIT1();            // Gq done (G0 may pend)
    __syncthreads();

    // ---- Q fragments to registers ----
    uint32_t qh[5][4], qlo[5][4];
    #pragma unroll
    for (int ks = 0; ks < 5; ks++) {
        const uint32_t ao = 2u * ((w * 16 + arow) * QS + ks * 16 + adim);
        ldm_x4(qh[ks],  sb + OFF_QH + ao);
        ldm_x4(qlo[ks], sb + OFF_QL + ao);
    }
    __syncthreads();       // Q region free -> becomes buffer 1

    if (ntiles > 1) issue_kv(sb, 1, kvbase + BK, t);
    CP_COMMIT();           // G1

    float O[8][4];
    #pragma unroll
    for (int i = 0; i < 8; i++)
        { O[i][0]=0.f; O[i][1]=0.f; O[i][2]=0.f; O[i][3]=0.f; }
    float la0 = 0.f, la1 = 0.f;
    const int rA = q0 + w * 16 + g;
    const int rB = rA + 8;

    for (int kt = 0; kt < ntiles; kt++) {
        const int k0 = kt * BK;
        const int buf = kt & 1;
        CP_WAIT1();        // tile kt ready (kt+1 may pend)
        __syncthreads();

        const bool active = !cz || (q0 + w * 16 + 15 >= k0);
        if (active) {
            const bool maskT = cz && (k0 + BK - 1 > q0 + w * 16);
            const uint32_t khO = sb + kh_off(buf), klO = sb + kl_off(buf);
            const uint32_t vhO = sb + vh_off(buf), vlO = sb + vl_off(buf);

            // ---- S = Q'K^T (3 bf16 passes), software-pipelined frags ----
            uint32_t pa[4][4];
            const int keyb = (ln >> 4) * 8 + (ln & 7);
            const int dsel = ((ln >> 3) & 1) * 8;
            #pragma unroll
            for (int nbi = 0; nbi < 4; nbi++) {
                const int nbp = (nbi + wrot) & 3;       // rotated key-block order
                const uint32_t krow = (uint32_t)(nbp * 16 + keyb) * 176u;
                float s0[4] = {0.f,0.f,0.f,0.f};
                float s1[4] = {0.f,0.f,0.f,0.f};
                uint32_t bf[2][4], lf[2][4];
                ldm_x4(bf[0], khO + krow + (uint32_t)(dsel) * 2u);
                ldm_x4(lf[0], klO + krow + (uint32_t)(dsel) * 2u);
                #pragma unroll
                for (int ks = 0; ks < 5; ks++) {
                    const int cur = ks & 1, nxt = cur ^ 1;
                    if (ks < 4) {                        // prefetch ks+1 frags
                        const uint32_t dnx = (uint32_t)((ks + 1) * 16 + dsel) * 2u;
                        ldm_x4(bf[nxt], khO + krow + dnx);
                        ldm_x4(lf[nxt], klO + krow + dnx);
                    }
                    mma_bf16(s0, qh[ks],  bf[cur]);  mma_bf16(s1, qh[ks],  bf[cur] + 2);
                    mma_bf16(s0, qh[ks],  lf[cur]);  mma_bf16(s1, qh[ks],  lf[cur] + 2);
                    mma_bf16(s0, qlo[ks], bf[cur]);  mma_bf16(s1, qlo[ks], bf[cur] + 2);
                }
                float p00 = __expf(s0[0] + SHIFT), p01 = __expf(s0[1] + SHIFT);
                float p02 = __expf(s0[2] + SHIFT), p03 = __expf(s0[3] + SHIFT);
                float p10 = __expf(s1[0] + SHIFT), p11 = __expf(s1[1] + SHIFT);
                float p12 = __expf(s1[2] + SHIFT), p13 = __expf(s1[3] + SHIFT);
                if (maskT) {
                    const int kb0 = k0 + nbp * 16 + tg * 2;
                    const int kb1 = kb0 + 8;
                    if (kb0     > rA) p00 = 0.f;
                    if (kb0 + 1 > rA) p01 = 0.f;
                    if (kb0     > rB) p02 = 0.f;
                    if (kb0 + 1 > rB) p03 = 0.f;
                    if (kb1     > rA) p10 = 0.f;
                    if (kb1 + 1 > rA) p11 = 0.f;
                    if (kb1     > rB) p12 = 0.f;
                    if (kb1 + 1 > rB) p13 = 0.f;
                }
                const uint32_t a0 = cvt_bf16x2(p00, p01);
                const uint32_t a1 = cvt_bf16x2(p02, p03);
                const uint32_t a2 = cvt_bf16x2(p10, p11);
                const uint32_t a3 = cvt_bf16x2(p12, p13);
                pa[nbp][0] = a0; pa[nbp][1] = a1; pa[nbp][2] = a2; pa[nbp][3] = a3;
                // l from ROUNDED weights so rounding cancels in normalization
                la0 += __uint_as_float(a0 << 16) + __uint_as_float(a0 & 0xffff0000u)
                     + __uint_as_float(a2 << 16) + __uint_as_float(a2 & 0xffff0000u);
                la1 += __uint_as_float(a1 << 16) + __uint_as_float(a1 & 0xffff0000u)
                     + __uint_as_float(a3 << 16) + __uint_as_float(a3 & 0xffff0000u);
            }

            // ---- O += P * (Vhi + Vlo), pipelined over 16 (i,np) steps ----
            const int vr = ln & 15;
            const int vcb = (ln >> 4) * 8;
            uint32_t vh[2][4], vl[2][4];
            {
                const int i0 = wrot;                     // rotated key-block order
                const uint32_t off0 = (uint32_t)(i0 * 16 + vr) * 144u + (uint32_t)(vcb) * 2u;
                ldm_x4t(vh[0], vhO + off0);
                ldm_x4t(vl[0], vlO + off0);
            }
            #pragma unroll
            for (int j = 0; j < 16; j++) {
                const int cur = j & 1, nxt = cur ^ 1;
                const int i  = ((j >> 2) + wrot) & 3;    // key block (rotated)
                const int np = j & 3;                    // output dim pair
                if (j < 15) {                            // prefetch j+1 frags
                    const int jn = j + 1;
                    const int in  = ((jn >> 2) + wrot) & 3;
                    const int npn = jn & 3;
                    const uint32_t offn = (uint32_t)(in * 16 + vr) * 144u
                                        + (uint32_t)(npn * 16 + vcb) * 2u;
                    ldm_x4t(vh[nxt], vhO + offn);
                    ldm_x4t(vl[nxt], vlO + offn);
                }
                mma_bf16(O[2*np],     pa[i], vh[cur]);
                mma_bf16(O[2*np + 1], pa[i], vh[cur] + 2);
                mma_bf16(O[2*np],     pa[i], vl[cur]);
                mma_bf16(O[2*np + 1], pa[i], vl[cur] + 2);
            }
        }

        __syncthreads();   // all warps done reading buf
        if (kt + 2 < ntiles) issue_kv(sb, buf, kvbase + (kt + 2) * BK, t);
        CP_COMMIT();
    }

    // ---- epilogue ----
    la0 += __shfl_xor_sync(0xffffffffu, la0, 1);
    la0 += __shfl_xor_sync(0xffffffffu, la0, 2);
    la1 += __shfl_xor_sync(0xffffffffu, la1, 1);
    la1 += __shfl_xor_sync(0xffffffffu, la1, 2);
    const float il0 = 1.0f / la0;
    const float il1 = 1.0f / la1;

    float y[8][4];
    float ss0 = 0.f, ss1 = 0.f;
    #pragma unroll
    for (int nb = 0; nb < 8; nb++) {
        y[nb][0] = O[nb][0] * il0;  y[nb][1] = O[nb][1] * il0;
        y[nb][2] = O[nb][2] * il1;  y[nb][3] = O[nb][3] * il1;
        ss0 += y[nb][0]*y[nb][0] + y[nb][1]*y[nb][1];
        ss1 += y[nb][2]*y[nb][2] + y[nb][3]*y[nb][3];
    }
    ss0 += __shfl_xor_sync(0xffffffffu, ss0, 1);
    ss0 += __shfl_xor_sync(0xffffffffu, ss0, 2);
    ss1 += __shfl_xor_sync(0xffffffffu, ss1, 1);
    ss1 += __shfl_xor_sync(0xffffffffu, ss1, 2);
    const float tc0 = sqrtf(ss0 + 1.0f);
    const float tc1 = sqrtf(ss1 + 1.0f);

    float* o0 = Og + obase + (size_t)rA * D;
    float* o1 = Og + obase + (size_t)rB * D;
    #pragma unroll
    for (int nb = 0; nb < 8; nb++) {
        const int d = nb * 8 + tg * 2;
        o0[1 + d] = y[nb][0];  o0[2 + d] = y[nb][1];
        o1[1 + d] = y[nb][2];  o1[2 + d] = y[nb][3];
    }
    if (tg == 0) { o0[0] = tc0; o1[0] = tc1; }
}

extern "C" void kernel_launch(void* const* d_in, const int* in_sizes, int n_in,
                              void* d_out, int out_size)
{
    const float* Q  = (const float*)d_in[0];
    const float* K  = (const float*)d_in[1];
    const float* V  = (const float*)d_in[2];
    const int* causal = (const int*)d_in[3];
    float* out = (float*)d_out;

    const int BH = in_sizes[0] / (N_SEQ * D);   // 32

    prep_kernel<<<BH * N_SEQ / 8, 256>>>(Q, K, V, BH);

    cudaFuncSetAttribute(lorentz_attn_mma,
                         cudaFuncAttributeMaxDynamicSharedMemorySize, SMEM_TOTAL);
    dim3 grid(N_SEQ / BQ, BH);
    lorentz_attn_mma<<<grid, THREADS, SMEM_TOTAL>>>(causal, out);
}

// round 13
// speedup vs baseline: 1.2374x; 1.2374x over previous
#include <cuda_runtime.h>
#include <cuda_bf16.h>
#include <cuda_fp16.h>
#include <stdint.h>
#include <math.h>

// QuadraticLorentzAttention via mma.sync (plain-sm_100-safe).
// s = <qs,ks> - t_q t_k <= -1 on-hyperboloid => no-max softmax, p=exp(s+64).
// R12: time product exact in fp32 scalar (removed from MMA; ks 5->4);
// QK in fp16 hi/lo (3 passes); PV P bf16 x V bf16 hi/lo (2 passes);
// unified 144B strides; smem 74240. Simple R6-style body (R10 pipelining
// was neutral -> reverted).

namespace {
constexpr int N_SEQ = 2048;
constexpr int D     = 65;
constexpr int BQ    = 128;    // 8 warps x 16 query rows
constexpr int BK    = 64;
constexpr int THREADS = 256;
constexpr int BHMAX = 32;
constexpr float SHIFT = 64.0f;

// per-buffer layout (bytes): KH 0, KL 9216, VH 18432, VL 27648, TK 36864(256B)
constexpr uint32_t BUFSZ  = 37120;
constexpr uint32_t OFF_QH = 37120;   // Q staging overlays buffer 1
constexpr uint32_t OFF_QL = 55552;
constexpr uint32_t SMEM_TOTAL = 74240;
}

// global scratch (written by prep kernel each launch)
__device__ __align__(128) __half g_qh[(size_t)BHMAX * N_SEQ * 64];
__device__ __align__(128) __half g_ql[(size_t)BHMAX * N_SEQ * 64];
__device__ __align__(128) __half g_kh[(size_t)BHMAX * N_SEQ * 64];
__device__ __align__(128) __half g_kl[(size_t)BHMAX * N_SEQ * 64];
__device__ __align__(128) __nv_bfloat16 g_vh[(size_t)BHMAX * N_SEQ * 64];
__device__ __align__(128) __nv_bfloat16 g_vl[(size_t)BHMAX * N_SEQ * 64];
__device__ __align__(128) float g_tq[(size_t)BHMAX * N_SEQ];
__device__ __align__(128) float g_tk[(size_t)BHMAX * N_SEQ];

__device__ __forceinline__ uint32_t smem_u32(const void* p) {
    uint32_t a;
    asm("{ .reg .u64 t; cvta.to.shared.u64 t, %1; cvt.u32.u64 %0, t; }" : "=r"(a) : "l"(p));
    return a;
}
__device__ __forceinline__ void ldm_x4(uint32_t* r, uint32_t a) {
    asm volatile("ldmatrix.sync.aligned.m8n8.x4.shared.b16 {%0,%1,%2,%3}, [%4];"
                 : "=r"(r[0]), "=r"(r[1]), "=r"(r[2]), "=r"(r[3]) : "r"(a) : "memory");
}
__device__ __forceinline__ void ldm_x4t(uint32_t* r, uint32_t a) {
    asm volatile("ldmatrix.sync.aligned.m8n8.x4.trans.shared.b16 {%0,%1,%2,%3}, [%4];"
                 : "=r"(r[0]), "=r"(r[1]), "=r"(r[2]), "=r"(r[3]) : "r"(a) : "memory");
}
__device__ __forceinline__ void mma_bf16(float* c, const uint32_t* a, const uint32_t* b) {
    asm volatile("mma.sync.aligned.m16n8k16.row.col.f32.bf16.bf16.f32 "
                 "{%0,%1,%2,%3}, {%4,%5,%6,%7}, {%8,%9}, {%0,%1,%2,%3};"
                 : "+f"(c[0]), "+f"(c[1]), "+f"(c[2]), "+f"(c[3])
                 : "r"(a[0]), "r"(a[1]), "r"(a[2]), "r"(a[3]), "r"(b[0]), "r"(b[1]));
}
__device__ __forceinline__ void mma_f16(float* c, const uint32_t* a, const uint32_t* b) {
    asm volatile("mma.sync.aligned.m16n8k16.row.col.f32.f16.f16.f32 "
                 "{%0,%1,%2,%3}, {%4,%5,%6,%7}, {%8,%9}, {%0,%1,%2,%3};"
                 : "+f"(c[0]), "+f"(c[1]), "+f"(c[2]), "+f"(c[3])
                 : "r"(a[0]), "r"(a[1]), "r"(a[2]), "r"(a[3]), "r"(b[0]), "r"(b[1]));
}
__device__ __forceinline__ uint32_t cvt_bf16x2(float lo, float hi) {
    uint32_t r;
    asm("cvt.rn.satfinite.bf16x2.f32 %0, %1, %2;" : "=r"(r) : "f"(hi), "f"(lo));
    return r;
}
__device__ __forceinline__ void cpa16(uint32_t dst, const void* src) {
    asm volatile("cp.async.cg.shared.global [%0], [%1], 16;" :: "r"(dst), "l"(src) : "memory");
}
#define CP_COMMIT() asm volatile("cp.async.commit_group;" ::: "memory")
#define CP_WAIT1()  asm volatile("cp.async.wait_group 1;" ::: "memory")

// ---------------- prep: fp32 -> fp16/bf16 hi-lo global layout ----------------
__global__ void __launch_bounds__(256)
prep_kernel(const float* __restrict__ Q, const float* __restrict__ K,
            const float* __restrict__ V, int BH)
{
    const int row = blockIdx.x * 8 + (threadIdx.x >> 5);
    const int ln  = threadIdx.x & 31;
    if (row >= BH * N_SEQ) return;
    const float* q = Q + (size_t)row * D;
    const float* k = K + (size_t)row * D;
    const float* v = V + (size_t)row * D;
    const size_t o = (size_t)row * 64;

    #pragma unroll
    for (int h = 0; h < 2; h++) {
        const int d = ln + 32 * h;
        const float qv = q[1 + d], kv = k[1 + d], vv = v[1 + d];
        __half xh;
        xh = __float2half_rn(qv); g_qh[o + d] = xh; g_ql[o + d] = __float2half_rn(qv - __half2float(xh));
        xh = __float2half_rn(kv); g_kh[o + d] = xh; g_kl[o + d] = __float2half_rn(kv - __half2float(xh));
        __nv_bfloat16 xb;
        xb = __float2bfloat16(vv); g_vh[o + d] = xb; g_vl[o + d] = __float2bfloat16(vv - __bfloat162float(xb));
    }
    if (ln == 0) {
        g_tq[row] = q[0];
        g_tk[row] = k[0];
    }
}

// ---------------- main attention kernel ----------------
extern __shared__ char smem_raw[];

__device__ __forceinline__ void issue_kv(uint32_t sb, int buf, int kbase, int t) {
    const uint32_t base = sb + (uint32_t)buf * BUFSZ;
    #pragma unroll
    for (int it = 0; it < 9; it++) {
        const int c = t + it * 256;
        if (c < 2048) {
            const int mat = c >> 9;           // 0 KH, 1 KL, 2 VH, 3 VL
            const int cc = c & 511;
            const int row = cc >> 3, ch = cc & 7;
            const size_t so = (size_t)(kbase + row) * 64 + ch * 8;
            const void* src;
            if      (mat == 0) src = g_kh + so;
            else if (mat == 1) src = g_kl + so;
            else if (mat == 2) src = g_vh + so;
            else               src = g_vl + so;
            cpa16(base + (uint32_t)mat * 9216u + row * 144 + ch * 16, src);
        } else if (c < 2064) {
            const int i = c - 2048;
            cpa16(base + 36864u + i * 16, g_tk + kbase + i * 4);
        }
    }
}

__global__ void __launch_bounds__(THREADS, 2)
lorentz_attn_mma(const int* __restrict__ causal_p, float* __restrict__ Og)
{
    const uint32_t sb = smem_u32(smem_raw);
    const int t  = threadIdx.x;
    const int w  = t >> 5;
    const int ln = t & 31;
    const int g  = ln >> 2;
    const int tg = ln & 3;
    const int bh = blockIdx.y;
    const int q0 = (gridDim.x - 1 - blockIdx.x) * BQ;   // heavy causal tiles first
    const int cz = *causal_p;
    const size_t obase = (size_t)bh * N_SEQ * D;

    const int arow = (ln & 7) + ((ln >> 3) & 1) * 8;    // A-frag addressing
    const int adim = (ln >> 4) * 8;
    const int ntiles = cz ? (q0 >> 6) + 2 : (N_SEQ / BK);
    const int qbase = bh * N_SEQ + q0;
    const int kvbase = bh * N_SEQ;

    // ---- stage Q (group Gq) into upper region, then K/V tile 0 (G0) ----
    #pragma unroll
    for (int it = 0; it < 8; it++) {
        const int c = t + it * 256;                     // 0..2047
        const int half = c >> 10;
        const int cc = c & 1023;
        const int row = cc >> 3, ch = cc & 7;
        const __half* src = (half ? g_ql : g_qh) + (size_t)(qbase + row) * 64 + ch * 8;
        cpa16(sb + (half ? OFF_QL : OFF_QH) + row * 144 + ch * 16, src);
    }
    CP_COMMIT();
    issue_kv(sb, 0, kvbase, t);
    CP_COMMIT();

    // per-lane time coords for its 2 query rows
    const float tqA = g_tq[qbase + w * 16 + g];
    const float tqB = g_tq[qbase + w * 16 + g + 8];

    CP_WAIT1();            // Gq done (G0 may pend)
    __syncthreads();

    // ---- Q fragments to registers (fp16 hi/lo, 4 ks steps) ----
    uint32_t qh[4][4], qlo[4][4];
    #pragma unroll
    for (int ks = 0; ks < 4; ks++) {
        const uint32_t ao = (uint32_t)((w * 16 + arow) * 144 + (ks * 16 + adim) * 2);
        ldm_x4(qh[ks],  sb + OFF_QH + ao);
        ldm_x4(qlo[ks], sb + OFF_QL + ao);
    }
    __syncthreads();       // Q region free -> becomes buffer 1

    if (ntiles > 1) issue_kv(sb, 1, kvbase + BK, t);
    CP_COMMIT();           // G1

    float O[8][4];
    #pragma unroll
    for (int i = 0; i < 8; i++)
        { O[i][0]=0.f; O[i][1]=0.f; O[i][2]=0.f; O[i][3]=0.f; }
    float la0 = 0.f, la1 = 0.f;
    const int rA = q0 + w * 16 + g;
    const int rB = rA + 8;

    for (int kt = 0; kt < ntiles; kt++) {
        const int k0 = kt * BK;
        const int buf = kt & 1;
        CP_WAIT1();        // tile kt ready (kt+1 may pend)
        __syncthreads();

        const bool active = !cz || (q0 + w * 16 + 15 >= k0);
        if (active) {
            const bool maskT = cz && (k0 + BK - 1 > q0 + w * 16);
            const uint32_t bufb = (uint32_t)buf * BUFSZ;
            const uint32_t khO = sb + bufb;
            const uint32_t klO = khO + 9216u;
            const uint32_t vhO = khO + 18432u;
            const uint32_t vlO = khO + 27648u;
            const char* tkp = smem_raw + bufb + 36864u;

            // ---- S_spatial = Q'K^T (3 fp16 passes, 4 ks), exact time term ----
            uint32_t pa[4][4];
            const int keyb = (ln >> 4) * 8 + (ln & 7);
            const int dsel = ((ln >> 3) & 1) * 8;
            #pragma unroll
            for (int nbp = 0; nbp < 4; nbp++) {
                float s0[4] = {0.f,0.f,0.f,0.f};
                float s1[4] = {0.f,0.f,0.f,0.f};
                const uint32_t krow = (uint32_t)(nbp * 16 + keyb) * 144u;
                #pragma unroll
                for (int ks = 0; ks < 4; ks++) {
                    uint32_t b4[4], l4[4];
                    const uint32_t doff = (uint32_t)(ks * 16 + dsel) * 2u;
                    ldm_x4(b4, khO + krow + doff);
                    ldm_x4(l4, klO + krow + doff);
                    mma_f16(s0, qh[ks],  b4);     mma_f16(s1, qh[ks],  b4 + 2);
                    mma_f16(s0, qh[ks],  l4);     mma_f16(s1, qh[ks],  l4 + 2);
                    mma_f16(s0, qlo[ks], b4);     mma_f16(s1, qlo[ks], b4 + 2);
                }
                // exact fp32 time term: s = s_spatial - t_q t_k (+ SHIFT)
                const float2 tk01 = *(const float2*)(tkp + (nbp * 16 + tg * 2) * 4);
                const float2 tk89 = *(const float2*)(tkp + (nbp * 16 + 8 + tg * 2) * 4);
                float p00 = __expf(s0[0] + fmaf(-tqA, tk01.x, SHIFT));
                float p01 = __expf(s0[1] + fmaf(-tqA, tk01.y, SHIFT));
                float p02 = __expf(s0[2] + fmaf(-tqB, tk01.x, SHIFT));
                float p03 = __expf(s0[3] + fmaf(-tqB, tk01.y, SHIFT));
                float p10 = __expf(s1[0] + fmaf(-tqA, tk89.x, SHIFT));
                float p11 = __expf(s1[1] + fmaf(-tqA, tk89.y, SHIFT));
                float p12 = __expf(s1[2] + fmaf(-tqB, tk89.x, SHIFT));
                float p13 = __expf(s1[3] + fmaf(-tqB, tk89.y, SHIFT));
                if (maskT) {
                    const int kb0 = k0 + nbp * 16 + tg * 2;
                    const int kb1 = kb0 + 8;
                    if (kb0     > rA) p00 = 0.f;
                    if (kb0 + 1 > rA) p01 = 0.f;
                    if (kb0     > rB) p02 = 0.f;
                    if (kb0 + 1 > rB) p03 = 0.f;
                    if (kb1     > rA) p10 = 0.f;
                    if (kb1 + 1 > rA) p11 = 0.f;
                    if (kb1     > rB) p12 = 0.f;
                    if (kb1 + 1 > rB) p13 = 0.f;
                }
                // C-frag == PV A-frag layout: pack directly (P in bf16)
                const uint32_t a0 = cvt_bf16x2(p00, p01);
                const uint32_t a1 = cvt_bf16x2(p02, p03);
                const uint32_t a2 = cvt_bf16x2(p10, p11);
                const uint32_t a3 = cvt_bf16x2(p12, p13);
                pa[nbp][0] = a0; pa[nbp][1] = a1; pa[nbp][2] = a2; pa[nbp][3] = a3;
                // l from ROUNDED weights so rounding cancels in normalization
                la0 += __uint_as_float(a0 << 16) + __uint_as_float(a0 & 0xffff0000u)
                     + __uint_as_float(a2 << 16) + __uint_as_float(a2 & 0xffff0000u);
                la1 += __uint_as_float(a1 << 16) + __uint_as_float(a1 & 0xffff0000u)
                     + __uint_as_float(a3 << 16) + __uint_as_float(a3 & 0xffff0000u);
            }

            // ---- O += P * (Vhi + Vlo) ----
            const int vr = ln & 15;
            const int vcb = (ln >> 4) * 8;
            #pragma unroll
            for (int i = 0; i < 4; i++) {             // key blocks
                const uint32_t vrow = (uint32_t)(i * 16 + vr) * 144u;
                #pragma unroll
                for (int np = 0; np < 4; np++) {      // output dim pairs
                    uint32_t vh4[4], vl4[4];
                    const uint32_t off = vrow + (uint32_t)(np * 16 + vcb) * 2u;
                    ldm_x4t(vh4, vhO + off);
                    ldm_x4t(vl4, vlO + off);
                    mma_bf16(O[2*np],     pa[i], vh4);
                    mma_bf16(O[2*np + 1], pa[i], vh4 + 2);
                    mma_bf16(O[2*np],     pa[i], vl4);
                    mma_bf16(O[2*np + 1], pa[i], vl4 + 2);
                }
            }
        }

        __syncthreads();   // all warps done reading buf
        if (kt + 2 < ntiles) issue_kv(sb, buf, kvbase + (kt + 2) * BK, t);
        CP_COMMIT();
    }

    // ---- epilogue ----
    la0 += __shfl_xor_sync(0xffffffffu, la0, 1);
    la0 += __shfl_xor_sync(0xffffffffu, la0, 2);
    la1 += __shfl_xor_sync(0xffffffffu, la1, 1);
    la1 += __shfl_xor_sync(0xffffffffu, la1, 2);
    const float il0 = 1.0f / la0;
    const float il1 = 1.0f / la1;

    float y[8][4];
    float ss0 = 0.f, ss1 = 0.f;
    #pragma unroll
    for (int nb = 0; nb < 8; nb++) {
        y[nb][0] = O[nb][0] * il0;  y[nb][1] = O[nb][1] * il0;
        y[nb][2] = O[nb][2] * il1;  y[nb][3] = O[nb][3] * il1;
        ss0 += y[nb][0]*y[nb][0] + y[nb][1]*y[nb][1];
        ss1 += y[nb][2]*y[nb][2] + y[nb][3]*y[nb][3];
    }
    ss0 += __shfl_xor_sync(0xffffffffu, ss0, 1);
    ss0 += __shfl_xor_sync(0xffffffffu, ss0, 2);
    ss1 += __shfl_xor_sync(0xffffffffu, ss1, 1);
    ss1 += __shfl_xor_sync(0xffffffffu, ss1, 2);
    const float tc0 = sqrtf(ss0 + 1.0f);
    const float tc1 = sqrtf(ss1 + 1.0f);

    float* o0 = Og + obase + (size_t)rA * D;
    float* o1 = Og + obase + (size_t)rB * D;
    #pragma unroll
    for (int nb = 0; nb < 8; nb++) {
        const int d = nb * 8 + tg * 2;
        o0[1 + d] = y[nb][0];  o0[2 + d] = y[nb][1];
        o1[1 + d] = y[nb][2];  o1[2 + d] = y[nb][3];
    }
    if (tg == 0) { o0[0] = tc0; o1[0] = tc1; }
}

extern "C" void kernel_launch(void* const* d_in, const int* in_sizes, int n_in,
                              void* d_out, int out_size)
{
    const float* Q  = (const float*)d_in[0];
    const float* K  = (const float*)d_in[1];
    const float* V  = (const float*)d_in[2];
    const int* causal = (const int*)d_in[3];
    float* out = (float*)d_out;

    const int BH = in_sizes[0] / (N_SEQ * D);   // 32

    prep_kernel<<<BH * N_SEQ / 8, 256>>>(Q, K, V, BH);

    cudaFuncSetAttribute(lorentz_attn_mma,
                         cudaFuncAttributeMaxDynamicSharedMemorySize, SMEM_TOTAL);
    dim3 grid(N_SEQ / BQ, BH);
    lorentz_attn_mma<<<grid, THREADS, SMEM_TOTAL>>>(causal, out);
}

// round 16
// speedup vs baseline: 1.3808x; 1.1159x over previous
#include <cuda_runtime.h>
#include <cuda_fp16.h>
#include <stdint.h>
#include <math.h>
#include <math_constants.h>

// QuadraticLorentzAttention via mma.sync (plain-sm_100-safe).
// s = <qs,ks> - t_q t_k. R14/R15: TRUE running row-max softmax (fixes R13's
// fp16 underflow NaN): p = exp(s - m_row) in (0,1] always fits fp16.
// P fp16, V fp16 single pass (PV MMAs halved vs R12). QK fp16 hi/lo
// 3 passes, exact fp32 time term. Q persistent in smem; O rescale only
// when row max grows (warp-uniform skip). (R15: resubmit after broker
// infra failure.)

namespace {
constexpr int N_SEQ = 2048;
constexpr int D     = 65;
constexpr int BQ    = 128;    // 8 warps x 16 query rows
constexpr int BK    = 64;
constexpr int THREADS = 256;
constexpr int BHMAX = 32;

// per-buffer layout (bytes): KH 0, KL 9216, V 18432, TK 27648 (256B)
constexpr uint32_t BUFSZ  = 27904;
constexpr uint32_t OFF_QH = 55808;   // persistent Q (not overlaid)
constexpr uint32_t OFF_QL = 74240;
constexpr uint32_t SMEM_TOTAL = 92672;
}

// global scratch (written by prep kernel each launch)
__device__ __align__(128) __half g_qh[(size_t)BHMAX * N_SEQ * 64];
__device__ __align__(128) __half g_ql[(size_t)BHMAX * N_SEQ * 64];
__device__ __align__(128) __half g_kh[(size_t)BHMAX * N_SEQ * 64];
__device__ __align__(128) __half g_kl[(size_t)BHMAX * N_SEQ * 64];
__device__ __align__(128) __half g_v [(size_t)BHMAX * N_SEQ * 64];
__device__ __align__(128) float g_tq[(size_t)BHMAX * N_SEQ];
__device__ __align__(128) float g_tk[(size_t)BHMAX * N_SEQ];

__device__ __forceinline__ uint32_t smem_u32(const void* p) {
    uint32_t a;
    asm("{ .reg .u64 t; cvta.to.shared.u64 t, %1; cvt.u32.u64 %0, t; }" : "=r"(a) : "l"(p));
    return a;
}
__device__ __forceinline__ void ldm_x4(uint32_t* r, uint32_t a) {
    asm volatile("ldmatrix.sync.aligned.m8n8.x4.shared.b16 {%0,%1,%2,%3}, [%4];"
                 : "=r"(r[0]), "=r"(r[1]), "=r"(r[2]), "=r"(r[3]) : "r"(a) : "memory");
}
__device__ __forceinline__ void ldm_x4t(uint32_t* r, uint32_t a) {
    asm volatile("ldmatrix.sync.aligned.m8n8.x4.trans.shared.b16 {%0,%1,%2,%3}, [%4];"
                 : "=r"(r[0]), "=r"(r[1]), "=r"(r[2]), "=r"(r[3]) : "r"(a) : "memory");
}
__device__ __forceinline__ void mma_f16(float* c, const uint32_t* a, const uint32_t* b) {
    asm volatile("mma.sync.aligned.m16n8k16.row.col.f32.f16.f16.f32 "
                 "{%0,%1,%2,%3}, {%4,%5,%6,%7}, {%8,%9}, {%0,%1,%2,%3};"
                 : "+f"(c[0]), "+f"(c[1]), "+f"(c[2]), "+f"(c[3])
                 : "r"(a[0]), "r"(a[1]), "r"(a[2]), "r"(a[3]), "r"(b[0]), "r"(b[1]));
}
__device__ __forceinline__ uint32_t cvt_f16x2(float lo, float hi) {
    uint32_t r;
    asm("cvt.rn.satfinite.f16x2.f32 %0, %1, %2;" : "=r"(r) : "f"(hi), "f"(lo));
    return r;
}
__device__ __forceinline__ float hsum2(uint32_t h) {
    const __half2 x = *reinterpret_cast<const __half2*>(&h);
    const float2 f = __half22float2(x);
    return f.x + f.y;
}
__device__ __forceinline__ void cpa16(uint32_t dst, const void* src) {
    asm volatile("cp.async.cg.shared.global [%0], [%1], 16;" :: "r"(dst), "l"(src) : "memory");
}
#define CP_COMMIT() asm volatile("cp.async.commit_group;" ::: "memory")
#define CP_WAIT1()  asm volatile("cp.async.wait_group 1;" ::: "memory")

// ---------------- prep: fp32 -> fp16 hi/lo + time coords ----------------
__global__ void __launch_bounds__(256)
prep_kernel(const float* __restrict__ Q, const float* __restrict__ K,
            const float* __restrict__ V, int BH)
{
    const int row = blockIdx.x * 8 + (threadIdx.x >> 5);
    const int ln  = threadIdx.x & 31;
    if (row >= BH * N_SEQ) return;
    const float* q = Q + (size_t)row * D;
    const float* k = K + (size_t)row * D;
    const float* v = V + (size_t)row * D;
    const size_t o = (size_t)row * 64;

    #pragma unroll
    for (int h = 0; h < 2; h++) {
        const int d = ln + 32 * h;
        const float qv = q[1 + d], kv = k[1 + d], vv = v[1 + d];
        __half xh;
        xh = __float2half_rn(qv); g_qh[o + d] = xh; g_ql[o + d] = __float2half_rn(qv - __half2float(xh));
        xh = __float2half_rn(kv); g_kh[o + d] = xh; g_kl[o + d] = __float2half_rn(kv - __half2float(xh));
        g_v[o + d] = __float2half_rn(vv);
    }
    if (ln == 0) {
        g_tq[row] = q[0];
        g_tk[row] = k[0];
    }
}

// ---------------- main attention kernel ----------------
extern __shared__ char smem_raw[];

__device__ __forceinline__ void issue_kv(uint32_t sb, int buf, int kbase, int t) {
    const uint32_t base = sb + (uint32_t)buf * BUFSZ;
    #pragma unroll
    for (int it = 0; it < 7; it++) {
        const int c = t + it * 256;
        if (c < 1536) {
            const int mat = c >> 9;           // 0 KH, 1 KL, 2 V
            const int cc = c & 511;
            const int row = cc >> 3, ch = cc & 7;
            const size_t so = (size_t)(kbase + row) * 64 + ch * 8;
            const void* src;
            if      (mat == 0) src = g_kh + so;
            else if (mat == 1) src = g_kl + so;
            else               src = g_v  + so;
            cpa16(base + (uint32_t)mat * 9216u + row * 144 + ch * 16, src);
        } else if (c < 1552) {
            const int i = c - 1536;
            cpa16(base + 27648u + i * 16, g_tk + kbase + i * 4);
        }
    }
}

__global__ void __launch_bounds__(THREADS, 2)
lorentz_attn_mma(const int* __restrict__ causal_p, float* __restrict__ Og)
{
    const uint32_t sb = smem_u32(smem_raw);
    const int t  = threadIdx.x;
    const int w  = t >> 5;
    const int ln = t & 31;
    const int g  = ln >> 2;
    const int tg = ln & 3;
    const int bh = blockIdx.y;
    const int q0 = (gridDim.x - 1 - blockIdx.x) * BQ;   // heavy causal tiles first
    const int cz = *causal_p;
    const size_t obase = (size_t)bh * N_SEQ * D;
    const float NEG_INF = -CUDART_INF_F;

    const int arow = (ln & 7) + ((ln >> 3) & 1) * 8;    // A-frag addressing
    const int adim = (ln >> 4) * 8;
    const int ntiles = cz ? (q0 >> 6) + 2 : (N_SEQ / BK);   // always >= 2
    const int qbase = bh * N_SEQ + q0;
    const int kvbase = bh * N_SEQ;

    // ---- stage Q (persistent region), then K/V tiles 0 and 1 ----
    #pragma unroll
    for (int it = 0; it < 8; it++) {
        const int c = t + it * 256;                     // 0..2047
        const int half = c >> 10;
        const int cc = c & 1023;
        const int row = cc >> 3, ch = cc & 7;
        const __half* src = (half ? g_ql : g_qh) + (size_t)(qbase + row) * 64 + ch * 8;
        cpa16(sb + (half ? OFF_QL : OFF_QH) + row * 144 + ch * 16, src);
    }
    CP_COMMIT();           // Gq
    issue_kv(sb, 0, kvbase, t);
    CP_COMMIT();           // G0
    issue_kv(sb, 1, kvbase + BK, t);
    CP_COMMIT();           // G1 (ntiles >= 2 always)

    // per-lane time coords for its 2 query rows
    const float tqA = g_tq[qbase + w * 16 + g];
    const float tqB = g_tq[qbase + w * 16 + g + 8];

    float O[8][4];
    #pragma unroll
    for (int i = 0; i < 8; i++)
        { O[i][0]=0.f; O[i][1]=0.f; O[i][2]=0.f; O[i][3]=0.f; }
    float la0 = 0.f, la1 = 0.f;
    float mA = NEG_INF, mB = NEG_INF;
    const int rA = q0 + w * 16 + g;
    const int rB = rA + 8;

    const int keyb = (ln >> 4) * 8 + (ln & 7);
    const int dsel = ((ln >> 3) & 1) * 8;
    const int vr  = ln & 15;
    const int vcb = (ln >> 4) * 8;

    for (int kt = 0; kt < ntiles; kt++) {
        const int k0 = kt * BK;
        const int buf = kt & 1;
        CP_WAIT1();        // groups through tile kt complete (kt+1 may pend)
        __syncthreads();

        const bool active = !cz || (q0 + w * 16 + 15 >= k0);
        if (active) {
            const bool maskT = cz && (k0 + BK - 1 > q0 + w * 16);
            const uint32_t bufb = (uint32_t)buf * BUFSZ;
            const uint32_t khO = sb + bufb;
            const uint32_t klO = khO + 9216u;
            const uint32_t vO  = khO + 18432u;
            const char* tkp = smem_raw + bufb + 27648u;

            // ---- phase A: S_spatial for all 4 key blocks (3 fp16 passes) ----
            float s[4][8];
            #pragma unroll
            for (int nbp = 0; nbp < 4; nbp++)
                #pragma unroll
                for (int i = 0; i < 8; i++) s[nbp][i] = 0.f;

            #pragma unroll
            for (int ks = 0; ks < 4; ks++) {
                uint32_t qhf[4], qlf[4];
                const uint32_t ao = (uint32_t)((w * 16 + arow) * 144 + (ks * 16 + adim) * 2);
                ldm_x4(qhf, sb + OFF_QH + ao);
                ldm_x4(qlf, sb + OFF_QL + ao);
                #pragma unroll
                for (int nbp = 0; nbp < 4; nbp++) {
                    uint32_t b4[4], l4[4];
                    const uint32_t krow = (uint32_t)(nbp * 16 + keyb) * 144u;
                    const uint32_t doff = (uint32_t)(ks * 16 + dsel) * 2u;
                    ldm_x4(b4, khO + krow + doff);
                    ldm_x4(l4, klO + krow + doff);
                    mma_f16(s[nbp] + 0, qhf, b4);  mma_f16(s[nbp] + 4, qhf, b4 + 2);
                    mma_f16(s[nbp] + 0, qhf, l4);  mma_f16(s[nbp] + 4, qhf, l4 + 2);
                    mma_f16(s[nbp] + 0, qlf, b4);  mma_f16(s[nbp] + 4, qlf, b4 + 2);
                }
            }

            // ---- exact fp32 time term + causal mask ----
            #pragma unroll
            for (int nbp = 0; nbp < 4; nbp++) {
                const float2 tk01 = *(const float2*)(tkp + (nbp * 16 + tg * 2) * 4);
                const float2 tk89 = *(const float2*)(tkp + (nbp * 16 + 8 + tg * 2) * 4);
                s[nbp][0] = fmaf(-tqA, tk01.x, s[nbp][0]);
                s[nbp][1] = fmaf(-tqA, tk01.y, s[nbp][1]);
                s[nbp][2] = fmaf(-tqB, tk01.x, s[nbp][2]);
                s[nbp][3] = fmaf(-tqB, tk01.y, s[nbp][3]);
                s[nbp][4] = fmaf(-tqA, tk89.x, s[nbp][4]);
                s[nbp][5] = fmaf(-tqA, tk89.y, s[nbp][5]);
                s[nbp][6] = fmaf(-tqB, tk89.x, s[nbp][6]);
                s[nbp][7] = fmaf(-tqB, tk89.y, s[nbp][7]);
                if (maskT) {
                    const int kb0 = k0 + nbp * 16 + tg * 2;
                    const int kb1 = kb0 + 8;
                    if (kb0     > rA) s[nbp][0] = NEG_INF;
                    if (kb0 + 1 > rA) s[nbp][1] = NEG_INF;
                    if (kb0     > rB) s[nbp][2] = NEG_INF;
                    if (kb0 + 1 > rB) s[nbp][3] = NEG_INF;
                    if (kb1     > rA) s[nbp][4] = NEG_INF;
                    if (kb1 + 1 > rA) s[nbp][5] = NEG_INF;
                    if (kb1     > rB) s[nbp][6] = NEG_INF;
                    if (kb1 + 1 > rB) s[nbp][7] = NEG_INF;
                }
            }

            // ---- running row max (tile 0 always has key 0 visible) ----
            float tmA = NEG_INF, tmB = NEG_INF;
            #pragma unroll
            for (int nbp = 0; nbp < 4; nbp++) {
                tmA = fmaxf(tmA, fmaxf(fmaxf(s[nbp][0], s[nbp][1]), fmaxf(s[nbp][4], s[nbp][5])));
                tmB = fmaxf(tmB, fmaxf(fmaxf(s[nbp][2], s[nbp][3]), fmaxf(s[nbp][6], s[nbp][7])));
            }
            tmA = fmaxf(tmA, __shfl_xor_sync(0xffffffffu, tmA, 1));
            tmA = fmaxf(tmA, __shfl_xor_sync(0xffffffffu, tmA, 2));
            tmB = fmaxf(tmB, __shfl_xor_sync(0xffffffffu, tmB, 1));
            tmB = fmaxf(tmB, __shfl_xor_sync(0xffffffffu, tmB, 2));
            const float mAn = fmaxf(mA, tmA);
            const float mBn = fmaxf(mB, tmB);
            if (!__all_sync(0xffffffffu, (mAn == mA) && (mBn == mB))) {
                const float cA = __expf(mA - mAn);   // 0 on first tile, 1 if unchanged
                const float cB = __expf(mB - mBn);
                #pragma unroll
                for (int nb = 0; nb < 8; nb++) {
                    O[nb][0] *= cA; O[nb][1] *= cA;
                    O[nb][2] *= cB; O[nb][3] *= cB;
                }
                la0 *= cA; la1 *= cB;
                mA = mAn; mB = mBn;
            }

            // ---- exp + pack P fp16 (p in (0,1], exactly fp16-safe) ----
            uint32_t pa[4][4];
            #pragma unroll
            for (int nbp = 0; nbp < 4; nbp++) {
                const float p00 = __expf(s[nbp][0] - mA);
                const float p01 = __expf(s[nbp][1] - mA);
                const float p02 = __expf(s[nbp][2] - mB);
                const float p03 = __expf(s[nbp][3] - mB);
                const float p10 = __expf(s[nbp][4] - mA);
                const float p11 = __expf(s[nbp][5] - mA);
                const float p12 = __expf(s[nbp][6] - mB);
                const float p13 = __expf(s[nbp][7] - mB);
                const uint32_t a0 = cvt_f16x2(p00, p01);
                const uint32_t a1 = cvt_f16x2(p02, p03);
                const uint32_t a2 = cvt_f16x2(p10, p11);
                const uint32_t a3 = cvt_f16x2(p12, p13);
                pa[nbp][0] = a0; pa[nbp][1] = a1; pa[nbp][2] = a2; pa[nbp][3] = a3;
                // l from ROUNDED weights so rounding cancels in normalization
                la0 += hsum2(a0) + hsum2(a2);
                la1 += hsum2(a1) + hsum2(a3);
            }

            // ---- O += P * V (single fp16 pass) ----
            #pragma unroll
            for (int i = 0; i < 4; i++) {             // key blocks
                const uint32_t vrow = (uint32_t)(i * 16 + vr) * 144u;
                #pragma unroll
                for (int np = 0; np < 4; np++) {      // output dim pairs
                    uint32_t v4[4];
                    ldm_x4t(v4, vO + vrow + (uint32_t)(np * 16 + vcb) * 2u);
                    mma_f16(O[2*np],     pa[i], v4);
                    mma_f16(O[2*np + 1], pa[i], v4 + 2);
                }
            }
        }

        __syncthreads();   // all warps done reading buf
        if (kt + 2 < ntiles) issue_kv(sb, buf, kvbase + (kt + 2) * BK, t);
        CP_COMMIT();
    }

    // ---- epilogue ----
    la0 += __shfl_xor_sync(0xffffffffu, la0, 1);
    la0 += __shfl_xor_sync(0xffffffffu, la0, 2);
    la1 += __shfl_xor_sync(0xffffffffu, la1, 1);
    la1 += __shfl_xor_sync(0xffffffffu, la1, 2);
    const float il0 = 1.0f / la0;      // la0 >= 1 (row max weight = 1)
    const float il1 = 1.0f / la1;

    float y[8][4];
    float ss0 = 0.f, ss1 = 0.f;
    #pragma unroll
    for (int nb = 0; nb < 8; nb++) {
        y[nb][0] = O[nb][0] * il0;  y[nb][1] = O[nb][1] * il0;
        y[nb][2] = O[nb][2] * il1;  y[nb][3] = O[nb][3] * il1;
        ss0 += y[nb][0]*y[nb][0] + y[nb][1]*y[nb][1];
        ss1 += y[nb][2]*y[nb][2] + y[nb][3]*y[nb][3];
    }
    ss0 += __shfl_xor_sync(0xffffffffu, ss0, 1);
    ss0 += __shfl_xor_sync(0xffffffffu, ss0, 2);
    ss1 += __shfl_xor_sync(0xffffffffu, ss1, 1);
    ss1 += __shfl_xor_sync(0xffffffffu, ss1, 2);
    const float tc0 = sqrtf(ss0 + 1.0f);
    const float tc1 = sqrtf(ss1 + 1.0f);

    float* o0 = Og + obase + (size_t)rA * D;
    float* o1 = Og + obase + (size_t)rB * D;
    #pragma unroll
    for (int nb = 0; nb < 8; nb++) {
        const int d = nb * 8 + tg * 2;
        o0[1 + d] = y[nb][0];  o0[2 + d] = y[nb][1];
        o1[1 + d] = y[nb][2];  o1[2 + d] = y[nb][3];
    }
    if (tg == 0) { o0[0] = tc0; o1[0] = tc1; }
}

extern "C" void kernel_launch(void* const* d_in, const int* in_sizes, int n_in,
                              void* d_out, int out_size)
{
    const float* Q  = (const float*)d_in[0];
    const float* K  = (const float*)d_in[1];
    const float* V  = (const float*)d_in[2];
    const int* causal = (const int*)d_in[3];
    float* out = (float*)d_out;

    const int BH = in_sizes[0] / (N_SEQ * D);   // 32

    prep_kernel<<<BH * N_SEQ / 8, 256>>>(Q, K, V, BH);

    cudaFuncSetAttribute(lorentz_attn_mma,
                         cudaFuncAttributeMaxDynamicSharedMemorySize, SMEM_TOTAL);
    dim3 grid(N_SEQ / BQ, BH);
    lorentz_attn_mma<<<grid, THREADS, SMEM_TOTAL>>>(causal, out);
}